// round 15
// baseline (speedup 1.0000x reference)
#include <cuda_runtime.h>
#include <cuda_fp16.h>
#include <math.h>
#include <stdint.h>

#define BB 4
#define NN_ 1024
#define DIM 256
#define HEADS 4
#define DH 64
#define DEPTH 4
#define MLP 1024
#define EPS 1e-5f
#define SCALE 0.0625f   // DIM^-0.5

// ---------------- scratch ----------------
__device__ float  g_x   [BB*NN_*DIM];            // residual (fp32)
__device__ float  g_xma [BB*NN_*DIM];            // Wg out (fp32, LN input)
__device__ __half g_Gh  [(long)BB*NN_*NN_];      // G fp16
__device__ __half g_bias[(long)BB*HEADS*NN_*NN_];
__device__ __half g_xnh [BB*NN_*DIM];            // LN1(x) / LN2(x) fp16
__device__ __half g_xmah[BB*NN_*DIM];            // relu(LN(xma)) fp16
__device__ __half g_gxh [BB*NN_*DIM];            // GX fp16
__device__ __half g_aoh [BB*NN_*DIM];            // attention out fp16
__device__ __half g_ffh [BB*NN_*MLP];            // gelu out fp16
__device__ __half g_xth [BB*DIM*NN_];            // x^T fp16 (GX B operand)
__device__ __half g_kh  [BB*NN_*DIM];
__device__ __half g_qh  [BB*NN_*DIM];
__device__ __half g_vth [BB*DIM*NN_];
__device__ __half g_wh  [3211264];               // transposed fp16 weights

#define OW_KV 0
#define OW_Q  524288
#define OW_O  786432
#define OW_1  1048576
#define OW_2  2097152
#define OW_G  3145728

// ---------------- helpers ----------------
__device__ __forceinline__ float warp_sum(float v) {
#pragma unroll
    for (int o = 16; o; o >>= 1) v += __shfl_xor_sync(0xffffffffu, v, o);
    return v;
}
__device__ __forceinline__ float warp_max(float v) {
#pragma unroll
    for (int o = 16; o; o >>= 1) v = fmaxf(v, __shfl_xor_sync(0xffffffffu, v, o));
    return v;
}
__device__ __forceinline__ float block_sum(float v, float* sh) {
    int lane = threadIdx.x & 31, w = threadIdx.x >> 5;
    v = warp_sum(v);
    if (lane == 0) sh[w] = v;
    __syncthreads();
    v = (lane < 8) ? sh[lane] : 0.0f;
    v = warp_sum(v);
    __syncthreads();
    return v;
}
__device__ __forceinline__ float block_max(float v, float* sh) {
    int lane = threadIdx.x & 31, w = threadIdx.x >> 5;
    v = warp_max(v);
    if (lane == 0) sh[w] = v;
    __syncthreads();
    v = (lane < 8) ? sh[lane] : -INFINITY;
    v = warp_max(v);
    __syncthreads();
    return v;
}
__device__ __forceinline__ uint32_t packh(float a, float b) {
    __half2 h = __floats2half2_rn(a, b);
    return *reinterpret_cast<uint32_t*>(&h);
}
__device__ __forceinline__ void mma_f16(float c[4], const uint32_t a[4], const uint32_t b[2]) {
    asm volatile(
        "mma.sync.aligned.m16n8k16.row.col.f32.f16.f16.f32 "
        "{%0,%1,%2,%3}, {%4,%5,%6,%7}, {%8,%9}, {%0,%1,%2,%3};"
        : "+f"(c[0]), "+f"(c[1]), "+f"(c[2]), "+f"(c[3])
        : "r"(a[0]), "r"(a[1]), "r"(a[2]), "r"(a[3]), "r"(b[0]), "r"(b[1]));
}
__device__ __forceinline__ uint32_t smem_u32(const void* p) {
    return (uint32_t)__cvta_generic_to_shared(p);
}
__device__ __forceinline__ void cpa16(uint32_t dst, const void* src) {
    asm volatile("cp.async.cg.shared.global [%0], [%1], 16;" :: "r"(dst), "l"(src));
}
__device__ __forceinline__ void cp_commit() { asm volatile("cp.async.commit_group;"); }
template <int N> __device__ __forceinline__ void cp_wait() {
    asm volatile("cp.async.wait_group %0;" :: "n"(N));
}

// ---------------- fp16 dense GEMM core: BM=128 BN=64 BK=64, m16n8k16, 3-stage ----------------
#define LAH 72
#define LBH 72
#define STGH 3
#define STAGE_H (128 * LAH + 64 * LBH)      // 13824 halves (27648 B)
#define SM_GH (STGH * STAGE_H * 2)          // 82944 B

template <int EPI>
__device__ __forceinline__ void gemm_core_h(
    const __half* __restrict__ A, const __half* __restrict__ Bt,
    void* __restrict__ Cv, const float* __restrict__ E, const float* __restrict__ bv,
    __half* __restrict__ H2,
    int K, int lda, int ldb, int ldc, int row0, int col0, __half* smh) {

    const int tid = threadIdx.x, wid = tid >> 5, lane = tid & 31;
    const int gid = lane >> 2, tg = lane & 3;
    const int wm0 = (wid >> 1) * 32, wn0 = (wid & 1) * 32;

    float acc[2][4][4];
#pragma unroll
    for (int i = 0; i < 2; i++)
#pragma unroll
        for (int j = 0; j < 4; j++)
#pragma unroll
            for (int k = 0; k < 4; k++) acc[i][j][k] = 0.0f;

    auto issue = [&](int buf, int t) {
        int k0 = t * 64;
        uint32_t as = smem_u32(smh + buf * STAGE_H);
        uint32_t bs = as + 128 * LAH * 2;
#pragma unroll
        for (int i = 0; i < 4; i++) {
            int q = tid + i * 256;
            int m = q >> 3, c16 = q & 7;
            cpa16(as + (m * LAH + c16 * 8) * 2,
                  A + (long)(row0 + m) * lda + k0 + c16 * 8);
        }
#pragma unroll
        for (int i = 0; i < 2; i++) {
            int q = tid + i * 256;
            int n = q >> 3, c16 = q & 7;
            cpa16(bs + (n * LBH + c16 * 8) * 2,
                  Bt + (long)(col0 + n) * ldb + k0 + c16 * 8);
        }
        cp_commit();
    };
    auto compute = [&](int buf) {
        const __half* ab = smh + buf * STAGE_H;
        const __half* bb = ab + 128 * LAH;
#pragma unroll
        for (int ks = 0; ks < 64; ks += 16) {
            uint32_t af[2][4], bf[4][2];
#pragma unroll
            for (int mt = 0; mt < 2; mt++) {
                const __half* p = ab + (wm0 + mt * 16 + gid) * LAH + ks + 2 * tg;
                af[mt][0] = *(const uint32_t*)p;
                af[mt][1] = *(const uint32_t*)(p + 8 * LAH);
                af[mt][2] = *(const uint32_t*)(p + 8);
                af[mt][3] = *(const uint32_t*)(p + 8 * LAH + 8);
            }
#pragma unroll
            for (int nt = 0; nt < 4; nt++) {
                const __half* p = bb + (wn0 + nt * 8 + gid) * LBH + ks + 2 * tg;
                bf[nt][0] = *(const uint32_t*)p;
                bf[nt][1] = *(const uint32_t*)(p + 8);
            }
#pragma unroll
            for (int mt = 0; mt < 2; mt++)
#pragma unroll
                for (int nt = 0; nt < 4; nt++)
                    mma_f16(acc[mt][nt], af[mt], bf[nt]);
        }
    };

    const int TILES = K / 64;
    issue(0, 0);
    issue(1, 1);
    int buf = 0, nxt = 2;
    for (int t = 0; t < TILES; t++) {
        cp_wait<STGH - 2>();
        __syncthreads();
        if (t + STGH - 1 < TILES) issue(nxt, t + STGH - 1);
        else cp_commit();
        compute(buf);
        buf = (buf + 1 == STGH) ? 0 : buf + 1;
        nxt = (nxt + 1 == STGH) ? 0 : nxt + 1;
    }

#pragma unroll
    for (int mt = 0; mt < 2; mt++)
#pragma unroll
        for (int nt = 0; nt < 4; nt++)
#pragma unroll
            for (int half = 0; half < 2; half++) {
                int r = row0 + wm0 + mt * 16 + gid + half * 8;
                int c = col0 + wn0 + nt * 8 + 2 * tg;
                float v0 = acc[mt][nt][half * 2 + 0];
                float v1 = acc[mt][nt][half * 2 + 1];
                if (EPI == 4) {
                    *(__half2*)((__half*)Cv + (long)r * ldc + c) = __floats2half2_rn(v0, v1);
                } else if (EPI == 5) {
                    __half* H = (__half*)Cv;
                    int bb2 = r >> 10, rl = r & 1023;
                    H[((long)bb2 * DIM + c) * NN_ + rl] = __float2half_rn(v0);
                    H[((long)bb2 * DIM + c + 1) * NN_ + rl] = __float2half_rn(v1);
                } else if (EPI == 3) {
                    v0 += bv[c];
                    v1 += bv[c + 1];
                    v0 = 0.5f * v0 * (1.0f + erff(v0 * 0.70710678118654752f));
                    v1 = 0.5f * v1 * (1.0f + erff(v1 * 0.70710678118654752f));
                    *(__half2*)((__half*)Cv + (long)r * ldc + c) = __floats2half2_rn(v0, v1);
                } else {
                    long off = (long)r * ldc + c;
                    if (EPI == 2 || EPI == 6) {
                        float2 e = *(const float2*)(E + off);
                        v0 += e.x + bv[c];
                        v1 += e.y + bv[c + 1];
                    }
                    float2 o; o.x = v0; o.y = v1;
                    *(float2*)((float*)Cv + off) = o;
                    if (EPI == 6) {
                        int bb2 = r >> 10, rl = r & 1023;
                        H2[((long)bb2 * DIM + c) * NN_ + rl] = __float2half_rn(v0);
                        H2[((long)bb2 * DIM + c + 1) * NN_ + rl] = __float2half_rn(v1);
                    }
                }
            }
}

template <int EPI>
__global__ __launch_bounds__(256, 2)
void mma_gemm_h(const __half* __restrict__ A, const __half* __restrict__ Bt,
                void* __restrict__ C, const float* __restrict__ E,
                const float* __restrict__ bv, __half* __restrict__ H2,
                int K, int lda, int ldb, int ldc,
                long Ab, long Bb, long Cb) {
    extern __shared__ __align__(16) __half smh[];
    int z = blockIdx.z;
    A += (long)z * Ab;
    Bt += (long)z * Bb;
    void* Cz = (EPI == 3 || EPI == 4 || EPI == 5)
               ? (void*)((__half*)C + (long)z * Cb)
               : (void*)((float*)C + (long)z * Cb);
    gemm_core_h<EPI>(A, Bt, Cz, E, bv, H2,
                     K, lda, ldb, ldc, blockIdx.y * 128, blockIdx.x * 64, smh);
}

// ---------------- LayerNorm row helper (fp16 out) ----------------
__device__ __forceinline__ void ln_row(const float* __restrict__ in, __half* __restrict__ out,
                                       const float* __restrict__ g, const float* __restrict__ bt,
                                       long row, int lane, int relu) {
    const float* p = in + row * DIM + lane * 8;
    float4 v0 = *(const float4*)p;
    float4 v1 = *(const float4*)(p + 4);
    float s = v0.x + v0.y + v0.z + v0.w + v1.x + v1.y + v1.z + v1.w;
    float q = v0.x * v0.x + v0.y * v0.y + v0.z * v0.z + v0.w * v0.w
            + v1.x * v1.x + v1.y * v1.y + v1.z * v1.z + v1.w * v1.w;
#pragma unroll
    for (int o = 16; o; o >>= 1) {
        s += __shfl_xor_sync(0xffffffffu, s, o);
        q += __shfl_xor_sync(0xffffffffu, q, o);
    }
    float mean = s * (1.0f / DIM);
    float var = q * (1.0f / DIM) - mean * mean;
    float rstd = rsqrtf(var + EPS);
    const float* gp = g + lane * 8;
    const float* bp = bt + lane * 8;
    float4 g0 = *(const float4*)gp, g1 = *(const float4*)(gp + 4);
    float4 b0 = *(const float4*)bp, b1 = *(const float4*)(bp + 4);
    float o8[8];
    o8[0] = (v0.x - mean) * rstd * g0.x + b0.x; o8[1] = (v0.y - mean) * rstd * g0.y + b0.y;
    o8[2] = (v0.z - mean) * rstd * g0.z + b0.z; o8[3] = (v0.w - mean) * rstd * g0.w + b0.w;
    o8[4] = (v1.x - mean) * rstd * g1.x + b1.x; o8[5] = (v1.y - mean) * rstd * g1.y + b1.y;
    o8[6] = (v1.z - mean) * rstd * g1.z + b1.z; o8[7] = (v1.w - mean) * rstd * g1.w + b1.w;
    if (relu) {
#pragma unroll
        for (int t = 0; t < 8; t++) o8[t] = fmaxf(o8[t], 0.0f);
    }
    union { __half2 h2[4]; uint4 u; } pk;
    pk.h2[0] = __floats2half2_rn(o8[0], o8[1]);
    pk.h2[1] = __floats2half2_rn(o8[2], o8[3]);
    pk.h2[2] = __floats2half2_rn(o8[4], o8[5]);
    pk.h2[3] = __floats2half2_rn(o8[6], o8[7]);
    *(uint4*)(out + row * DIM + lane * 8) = pk.u;
}

__global__ __launch_bounds__(256)
void ln_one(const float* __restrict__ in, __half* __restrict__ out,
            const float* __restrict__ g, const float* __restrict__ bt, int relu) {
    int w = threadIdx.x >> 5, lane = threadIdx.x & 31;
    ln_row(in, out, g, bt, (long)blockIdx.x * 8 + w, lane, relu);
}

// ---------------- M1: GX GEMM (blocks [0,128)) || LN1(x) (blocks [128,640)) ----------------
__global__ __launch_bounds__(256, 2)
void m1_kernel(const __half* __restrict__ Gh, const __half* __restrict__ xth,
               __half* __restrict__ gxh,
               const float* __restrict__ xsrc, __half* __restrict__ xnh,
               const float* __restrict__ g1, const float* __restrict__ b1v) {
    extern __shared__ __align__(16) __half smh[];
    int bid = blockIdx.x;
    if (bid < 128) {
        int bx = bid & 3, by = (bid >> 2) & 7, bz = bid >> 5;
        gemm_core_h<4>(Gh + (long)bz * NN_ * NN_, xth + (long)bz * DIM * NN_,
                       (void*)(gxh + (long)bz * NN_ * DIM), nullptr, nullptr, nullptr,
                       NN_, NN_, NN_, DIM, by * 128, bx * 64, smh);
    } else {
        int rb = bid - 128;                       // 512 blocks x 8 rows = 4096 rows
        int w = threadIdx.x >> 5, lane = threadIdx.x & 31;
        ln_row(xsrc, xnh, g1, b1v, (long)rb * 8 + w, lane, 0);
    }
}

// ---------------- M2: Wg GEMM (blocks [0,128)) || K/V GEMMs (blocks [128,384)) --------------
__global__ __launch_bounds__(256, 2)
void m2_kernel(const __half* __restrict__ gxh, const __half* __restrict__ WgT,
               float* __restrict__ xma,
               const __half* __restrict__ xnh, const __half* __restrict__ Wkvt) {
    extern __shared__ __align__(16) __half smh[];
    int bid = blockIdx.x;
    if (bid < 128) {
        int bx = bid & 3, by = bid >> 2;
        gemm_core_h<0>(gxh, WgT, (void*)xma, nullptr, nullptr, nullptr,
                       DIM, DIM, DIM, DIM, by * 128, bx * 64, smh);
    } else {
        int local = bid - 128;
        int bx = local & 7, by = local >> 3;
        if (bx < 4)
            gemm_core_h<4>(xnh, Wkvt, (void*)g_kh, nullptr, nullptr, nullptr,
                           DIM, DIM, DIM, DIM, by * 128, bx * 64, smh);
        else
            gemm_core_h<5>(xnh, Wkvt + 256 * DIM, (void*)g_vth, nullptr, nullptr, nullptr,
                           DIM, DIM, DIM, 0, by * 128, (bx - 4) * 64, smh);
    }
}

// ---------------- fused flash attention (R11-validated) ----------------
#define FL_SMEM ((128 * 72 + 2 * 128 * 72 + 2 * 64 * 136 + 2 * 128 * 136) * 2)

__global__ __launch_bounds__(256)
void flash_kernel(const __half* __restrict__ Qg, const __half* __restrict__ Kg,
                  const __half* __restrict__ Vtg, const __half* __restrict__ biasg,
                  __half* __restrict__ Og) {
    extern __shared__ __align__(16) __half smh[];
    __half* Qs = smh;
    __half* Ks = Qs + 128 * 72;
    __half* Vts = Ks + 2 * 128 * 72;
    __half* Bs = Vts + 2 * 64 * 136;

    const int i0 = blockIdx.x * 128;
    const int h = blockIdx.y, b = blockIdx.z;
    const __half* Qp = Qg + (long)b * NN_ * DIM + h * DH;
    const __half* Kp = Kg + (long)b * NN_ * DIM + h * DH;
    const __half* Vtp = Vtg + ((long)b * DIM + h * DH) * NN_;
    const __half* Bp = biasg + ((long)(b * HEADS + h)) * NN_ * NN_ + (long)i0 * NN_;

    const int tid = threadIdx.x, wid = tid >> 5, lane = tid & 31;
    const int gid = lane >> 2, tg = lane & 3;
    const int wm0 = wid * 16;

    auto issue_kv = [&](int buf, int j0) {
        uint32_t ks = smem_u32(Ks + buf * 128 * 72);
        uint32_t vs = smem_u32(Vts + buf * 64 * 136);
        uint32_t bsm = smem_u32(Bs + buf * 128 * 136);
#pragma unroll
        for (int t = 0; t < 4; t++) {
            int q = tid + t * 256;
            int n = q >> 3, c8 = q & 7;
            cpa16(ks + (n * 72 + c8 * 8) * 2, Kp + (long)(j0 + n) * DIM + c8 * 8);
        }
#pragma unroll
        for (int t = 0; t < 4; t++) {
            int q = tid + t * 256;
            int r = q >> 4, c16 = q & 15;
            cpa16(vs + (r * 136 + c16 * 8) * 2, Vtp + (long)r * NN_ + j0 + c16 * 8);
        }
#pragma unroll
        for (int t = 0; t < 8; t++) {
            int q = tid + t * 256;
            int r = q >> 4, c16 = q & 15;
            cpa16(bsm + (r * 136 + c16 * 8) * 2, Bp + (long)r * NN_ + j0 + c16 * 8);
        }
        cp_commit();
    };

    issue_kv(0, 0);

#pragma unroll
    for (int t = 0; t < 4; t++) {
        int q = tid + t * 256;
        int m = q >> 3, c8 = q & 7;
        *(uint4*)(Qs + m * 72 + c8 * 8) = *(const uint4*)(Qp + (long)(i0 + m) * DIM + c8 * 8);
    }

    float oacc[8][4];
#pragma unroll
    for (int i = 0; i < 8; i++)
#pragma unroll
        for (int j = 0; j < 4; j++) oacc[i][j] = 0.0f;
    float li0 = 0.0f, li1 = 0.0f;

    for (int t = 0; t < NN_ / 128; t++) {
        const int j0 = t * 128;
        const int buf = t & 1;
        cp_wait<0>();
        __syncthreads();
        if (t + 1 < NN_ / 128) issue_kv(buf ^ 1, j0 + 128);

        const __half* kb = Ks + buf * 128 * 72;
        const __half* vb = Vts + buf * 64 * 136;
        const __half* bsm = Bs + buf * 128 * 136;

        float s[16][4];
#pragma unroll
        for (int i = 0; i < 16; i++)
#pragma unroll
            for (int j = 0; j < 4; j++) s[i][j] = 0.0f;
#pragma unroll
        for (int ks = 0; ks < 64; ks += 16) {
            uint32_t a[4];
            const __half* pa = Qs + (wm0 + gid) * 72 + ks + 2 * tg;
            a[0] = *(const uint32_t*)pa;
            a[1] = *(const uint32_t*)(pa + 8 * 72);
            a[2] = *(const uint32_t*)(pa + 8);
            a[3] = *(const uint32_t*)(pa + 8 * 72 + 8);
#pragma unroll
            for (int nt = 0; nt < 16; nt++) {
                const __half* pb = kb + (nt * 8 + gid) * 72 + ks + 2 * tg;
                uint32_t bf[2] = { *(const uint32_t*)pb, *(const uint32_t*)(pb + 8) };
                mma_f16(s[nt], a, bf);
            }
        }

#pragma unroll
        for (int nt = 0; nt < 16; nt++) {
            const __half* pb0 = bsm + (wm0 + gid) * 136 + nt * 8 + 2 * tg;
            float2 e0 = __half22float2(*(const __half2*)pb0);
            float2 e1 = __half22float2(*(const __half2*)(pb0 + 8 * 136));
            s[nt][0] = __expf(fmaf(s[nt][0], SCALE, e0.x)); li0 += s[nt][0];
            s[nt][1] = __expf(fmaf(s[nt][1], SCALE, e0.y)); li0 += s[nt][1];
            s[nt][2] = __expf(fmaf(s[nt][2], SCALE, e1.x)); li1 += s[nt][2];
            s[nt][3] = __expf(fmaf(s[nt][3], SCALE, e1.y)); li1 += s[nt][3];
        }

#pragma unroll
        for (int ge = 0; ge < 16; ge += 2) {
            uint32_t pa4[4];
            pa4[0] = packh(s[ge][0], s[ge][1]);
            pa4[1] = packh(s[ge][2], s[ge][3]);
            pa4[2] = packh(s[ge + 1][0], s[ge + 1][1]);
            pa4[3] = packh(s[ge + 1][2], s[ge + 1][3]);
            int k0 = ge * 8;
#pragma unroll
            for (int nt = 0; nt < 8; nt++) {
                const __half* pb = vb + (nt * 8 + gid) * 136 + k0 + 2 * tg;
                uint32_t bf[2] = { *(const uint32_t*)pb, *(const uint32_t*)(pb + 8) };
                mma_f16(oacc[nt], pa4, bf);
            }
        }
    }

    li0 += __shfl_xor_sync(0xffffffffu, li0, 1);
    li0 += __shfl_xor_sync(0xffffffffu, li0, 2);
    li1 += __shfl_xor_sync(0xffffffffu, li1, 1);
    li1 += __shfl_xor_sync(0xffffffffu, li1, 2);
    float iv0 = 1.0f / li0, iv1 = 1.0f / li1;
#pragma unroll
    for (int nt = 0; nt < 8; nt++) {
        long off = ((long)b * NN_ + i0 + wm0 + gid) * DIM + h * DH + nt * 8 + 2 * tg;
        *(__half2*)(Og + off) = __floats2half2_rn(oacc[nt][0] * iv0, oacc[nt][1] * iv0);
        *(__half2*)(Og + off + 8 * DIM) = __floats2half2_rn(oacc[nt][2] * iv1, oacc[nt][3] * iv1);
    }
}

// ---------------- M0: merged transposes (blocks [0,off7)) || prep (blocks [off7, off7+4096)) -
struct TJobs {
    const float* src[7];
    __half* dst[7];
    int K[7], N[7];
    int off[8];
};

__global__ __launch_bounds__(256)
void m0_kernel(TJobs J, const float* __restrict__ ab) {
    __shared__ float tile[32][33];
    __shared__ float sh[32];
    int bid = blockIdx.x;
    int tid = threadIdx.x;
    if (bid < J.off[7]) {
        int j = 0;
        while (bid >= J.off[j + 1]) j++;
        int local = bid - J.off[j];
        int K = J.K[j], N = J.N[j];
        int tn = N >> 5;
        int per_z = tn * (K >> 5);
        int z = local / per_z, rem = local % per_z;
        int n0 = (rem % tn) * 32, k0 = (rem / tn) * 32;
        const float* src = J.src[j] + (long)z * K * N;
        __half* dst = J.dst[j] + (long)z * K * N;
        int tx = tid & 31, ty = tid >> 5;
#pragma unroll
        for (int i = 0; i < 32; i += 8)
            tile[ty + i][tx] = src[(long)(k0 + ty + i) * N + n0 + tx];
        __syncthreads();
#pragma unroll
        for (int i = 0; i < 32; i += 8)
            dst[(long)(n0 + ty + i) * K + k0 + tx] = __float2half_rn(tile[tx][ty + i]);
    } else {
        int pb = bid - J.off[7];
        int b = pb >> 10;
        int i = pb & 1023;
        const long BHNN = (long)BB * HEADS * NN_ * NN_;
        int j4 = tid * 4;
        float4 sa = make_float4(0, 0, 0, 0), sb = make_float4(0, 0, 0, 0);
#pragma unroll
        for (int h = 0; h < HEADS; h++) {
            long o = (((long)(b * HEADS + h) * NN_) + i) * NN_ + j4;
            float4 a0 = *(const float4*)(ab + o);
            float4 a1 = *(const float4*)(ab + BHNN + o);
            sa.x += a0.x; sa.y += a0.y; sa.z += a0.z; sa.w += a0.w;
            sb.x += a1.x; sb.y += a1.y; sb.z += a1.z; sb.w += a1.w;
            union { __half2 h2[2]; uint2 u; } pk;
            pk.h2[0] = __floats2half2_rn(a0.x + a1.x, a0.y + a1.y);
            pk.h2[1] = __floats2half2_rn(a0.z + a1.z, a0.w + a1.w);
            *(uint2*)(&g_bias[o]) = pk.u;
        }
        float val[4];
        val[0] = (sa.x * 0.25f) * (sb.x * 0.25f);
        val[1] = (sa.y * 0.25f) * (sb.y * 0.25f);
        val[2] = (sa.z * 0.25f) * (sb.z * 0.25f);
        val[3] = (sa.w * 0.25f) * (sb.w * 0.25f);
        float m = fmaxf(fmaxf(val[0], val[1]), fmaxf(val[2], val[3]));
        m = block_max(m, sh);
        float s = 0.0f;
#pragma unroll
        for (int t = 0; t < 4; t++) { val[t] = __expf(val[t] - m); s += val[t]; }
        s = block_sum(s, sh);
        float inv = 1.0f / s;
        long rowo = ((long)(b * NN_ + i)) * NN_ + j4;
        union { __half2 h2[2]; uint2 u; } gk;
        gk.h2[0] = __floats2half2_rn(val[0] * inv, val[1] * inv);
        gk.h2[1] = __floats2half2_rn(val[2] * inv, val[3] * inv);
        *(uint2*)(&g_Gh[rowo]) = gk.u;
    }
}

// ---------------- host ----------------
extern "C" void kernel_launch(void* const* d_in, const int* in_sizes, int n_in,
                              void* d_out, int out_size) {
    const float* x_in   = (const float*)d_in[0];
    const float* abias  = (const float*)d_in[1];
    const float* ln1_g  = (const float*)d_in[2];
    const float* ln1_b  = (const float*)d_in[3];
    const float* Wkv    = (const float*)d_in[4];
    const float* Wq     = (const float*)d_in[5];
    const float* Wo     = (const float*)d_in[6];
    const float* bo     = (const float*)d_in[7];
    const float* ln2_g  = (const float*)d_in[8];
    const float* ln2_b  = (const float*)d_in[9];
    const float* W1     = (const float*)d_in[10];
    const float* b1     = (const float*)d_in[11];
    const float* W2     = (const float*)d_in[12];
    const float* b2     = (const float*)d_in[13];
    const float* Wg     = (const float*)d_in[14];
    const float* lng_g  = (const float*)d_in[15];
    const float* lng_b  = (const float*)d_in[16];
    float* out = (float*)d_out;

    float *px, *pxma;
    __half *pGh, *pbias, *pxnh, *pxmah, *pgxh, *paoh, *pffh, *pxth, *pkh, *pqh, *pvth, *pwh;
    cudaGetSymbolAddress((void**)&px, g_x);
    cudaGetSymbolAddress((void**)&pxma, g_xma);
    cudaGetSymbolAddress((void**)&pGh, g_Gh);
    cudaGetSymbolAddress((void**)&pbias, g_bias);
    cudaGetSymbolAddress((void**)&pxnh, g_xnh);
    cudaGetSymbolAddress((void**)&pxmah, g_xmah);
    cudaGetSymbolAddress((void**)&pgxh, g_gxh);
    cudaGetSymbolAddress((void**)&paoh, g_aoh);
    cudaGetSymbolAddress((void**)&pffh, g_ffh);
    cudaGetSymbolAddress((void**)&pxth, g_xth);
    cudaGetSymbolAddress((void**)&pkh, g_kh);
    cudaGetSymbolAddress((void**)&pqh, g_qh);
    cudaGetSymbolAddress((void**)&pvth, g_vth);
    cudaGetSymbolAddress((void**)&pwh, g_wh);

    const int ROWS = BB * NN_;           // 4096
    dim3 blk(256);

    cudaFuncSetAttribute(mma_gemm_h<2>, cudaFuncAttributeMaxDynamicSharedMemorySize, SM_GH);
    cudaFuncSetAttribute(mma_gemm_h<3>, cudaFuncAttributeMaxDynamicSharedMemorySize, SM_GH);
    cudaFuncSetAttribute(mma_gemm_h<4>, cudaFuncAttributeMaxDynamicSharedMemorySize, SM_GH);
    cudaFuncSetAttribute(mma_gemm_h<6>, cudaFuncAttributeMaxDynamicSharedMemorySize, SM_GH);
    cudaFuncSetAttribute(m1_kernel, cudaFuncAttributeMaxDynamicSharedMemorySize, SM_GH);
    cudaFuncSetAttribute(m2_kernel, cudaFuncAttributeMaxDynamicSharedMemorySize, SM_GH);
    cudaFuncSetAttribute(flash_kernel, cudaFuncAttributeMaxDynamicSharedMemorySize, FL_SMEM);

    TJobs J;
    J.src[0] = Wkv;  J.dst[0] = pwh + OW_KV; J.K[0] = 256;  J.N[0] = 512;
    J.src[1] = Wq;   J.dst[1] = pwh + OW_Q;  J.K[1] = 256;  J.N[1] = 256;
    J.src[2] = Wo;   J.dst[2] = pwh + OW_O;  J.K[2] = 256;  J.N[2] = 256;
    J.src[3] = W1;   J.dst[3] = pwh + OW_1;  J.K[3] = 256;  J.N[3] = 1024;
    J.src[4] = W2;   J.dst[4] = pwh + OW_2;  J.K[4] = 1024; J.N[4] = 256;
    J.src[5] = Wg;   J.dst[5] = pwh + OW_G;  J.K[5] = 256;  J.N[5] = 256;
    J.src[6] = x_in; J.dst[6] = pxth;        J.K[6] = 1024; J.N[6] = 256;
    int nz[7] = {DEPTH, DEPTH, DEPTH, DEPTH, DEPTH, 1, BB};
    J.off[0] = 0;
    for (int j = 0; j < 7; j++)
        J.off[j + 1] = J.off[j] + nz[j] * (J.N[j] >> 5) * (J.K[j] >> 5);

    // M0: all transposes || prep
    m0_kernel<<<J.off[7] + BB * NN_, blk>>>(J, abias);

    for (int l = 0; l < DEPTH; l++) {
        const float* xcur = (l == 0) ? x_in : px;
        // M1: GX (128 gemm blocks) || xnh = LN1(x) (512 ln blocks)
        m1_kernel<<<640, blk, SM_GH>>>(pGh, pxth, pgxh, xcur, pxnh,
                                       ln1_g + l * DIM, ln1_b + l * DIM);
        // M2: xma = GX@Wg (128) || K/V from xnh (256)
        m2_kernel<<<384, blk, SM_GH>>>(pgxh, pwh + OW_G, pxma,
                                       pxnh, pwh + OW_KV + (long)l * 512 * DIM);
        // xmah = relu(LN(xma))
        ln_one<<<ROWS / 8, blk>>>(pxma, pxmah, lng_g, lng_b, 1);
        // q = xmah @ Wq
        mma_gemm_h<4><<<dim3(4, 32, 1), blk, SM_GH>>>(
            pxmah, pwh + OW_Q + (long)l * DIM * DIM, pqh, nullptr, nullptr, nullptr,
            DIM, DIM, DIM, DIM, 0, 0, 0);
        // flash -> aoh
        flash_kernel<<<dim3(NN_ / 128, HEADS, BB), blk, FL_SMEM>>>(pqh, pkh, pvth, pbias, paoh);
        // x = x + ao @ Wo + bo
        mma_gemm_h<2><<<dim3(4, 32, 1), blk, SM_GH>>>(
            paoh, pwh + OW_O + (long)l * DIM * DIM, px, xcur, bo + l * DIM, nullptr,
            DIM, DIM, DIM, DIM, 0, 0, 0);
        // xnh = LN2(x)
        ln_one<<<ROWS / 8, blk>>>(px, pxnh, ln2_g + l * DIM, ln2_b + l * DIM, 0);
        // ff = gelu(xnh @ W1 + b1)
        mma_gemm_h<3><<<dim3(16, 32, 1), blk, SM_GH>>>(
            pxnh, pwh + OW_1 + (long)l * MLP * DIM, pffh, nullptr, b1 + l * MLP, nullptr,
            DIM, DIM, DIM, MLP, 0, 0, 0);
        // x = x + ff @ W2 + b2 (+ x^T for next layer's GX)
        if (l == DEPTH - 1) {
            mma_gemm_h<2><<<dim3(4, 32, 1), blk, SM_GH>>>(
                pffh, pwh + OW_2 + (long)l * DIM * MLP, out, px, b2 + l * DIM, nullptr,
                MLP, MLP, MLP, DIM, 0, 0, 0);
        } else {
            mma_gemm_h<6><<<dim3(4, 32, 1), blk, SM_GH>>>(
                pffh, pwh + OW_2 + (long)l * DIM * MLP, px, px, b2 + l * DIM, pxth,
                MLP, MLP, MLP, DIM, 0, 0, 0);
        }
    }
}

// round 16
// speedup vs baseline: 1.0776x; 1.0776x over previous
#include <cuda_runtime.h>
#include <cuda_fp16.h>
#include <math.h>
#include <stdint.h>

#define BB 4
#define NN_ 1024
#define DIM 256
#define HEADS 4
#define DH 64
#define DEPTH 4
#define MLP 1024
#define EPS 1e-5f
#define SCALE 0.0625f   // DIM^-0.5

// ---------------- scratch ----------------
__device__ float  g_x   [BB*NN_*DIM];            // residual (fp32)
__device__ float  g_xma [BB*NN_*DIM];            // Wg out (fp32, LN input)
__device__ __half g_Gh  [(long)BB*NN_*NN_];      // G fp16
__device__ __half g_bias[(long)BB*HEADS*NN_*NN_];
__device__ __half g_xnh [BB*NN_*DIM];            // LN(x) / LN2(x) fp16
__device__ __half g_xmah[BB*NN_*DIM];            // relu(LN(xma)) fp16
__device__ __half g_gxh [BB*NN_*DIM];            // GX fp16
__device__ __half g_aoh [BB*NN_*DIM];            // attention out fp16
__device__ __half g_ffh [BB*NN_*MLP];            // gelu out fp16
__device__ __half g_xth [BB*DIM*NN_];            // x^T fp16 (GX B operand)
__device__ __half g_kh  [BB*NN_*DIM];
__device__ __half g_qh  [BB*NN_*DIM];
__device__ __half g_vth [BB*DIM*NN_];
__device__ __half g_wh  [3211264];               // transposed fp16 weights

// weight offsets in g_wh (halves)
#define OW_KV 0
#define OW_Q  524288
#define OW_O  786432
#define OW_1  1048576
#define OW_2  2097152
#define OW_G  3145728

// ---------------- helpers ----------------
__device__ __forceinline__ float warp_sum(float v) {
#pragma unroll
    for (int o = 16; o; o >>= 1) v += __shfl_xor_sync(0xffffffffu, v, o);
    return v;
}
__device__ __forceinline__ float warp_max(float v) {
#pragma unroll
    for (int o = 16; o; o >>= 1) v = fmaxf(v, __shfl_xor_sync(0xffffffffu, v, o));
    return v;
}
__device__ __forceinline__ float block_sum(float v, float* sh) {
    int lane = threadIdx.x & 31, w = threadIdx.x >> 5;
    v = warp_sum(v);
    if (lane == 0) sh[w] = v;
    __syncthreads();
    v = (lane < 8) ? sh[lane] : 0.0f;
    v = warp_sum(v);
    __syncthreads();
    return v;
}
__device__ __forceinline__ float block_max(float v, float* sh) {
    int lane = threadIdx.x & 31, w = threadIdx.x >> 5;
    v = warp_max(v);
    if (lane == 0) sh[w] = v;
    __syncthreads();
    v = (lane < 8) ? sh[lane] : -INFINITY;
    v = warp_max(v);
    __syncthreads();
    return v;
}
__device__ __forceinline__ uint32_t packh(float a, float b) {
    __half2 h = __floats2half2_rn(a, b);
    return *reinterpret_cast<uint32_t*>(&h);
}
__device__ __forceinline__ void mma_f16(float c[4], const uint32_t a[4], const uint32_t b[2]) {
    asm volatile(
        "mma.sync.aligned.m16n8k16.row.col.f32.f16.f16.f32 "
        "{%0,%1,%2,%3}, {%4,%5,%6,%7}, {%8,%9}, {%0,%1,%2,%3};"
        : "+f"(c[0]), "+f"(c[1]), "+f"(c[2]), "+f"(c[3])
        : "r"(a[0]), "r"(a[1]), "r"(a[2]), "r"(a[3]), "r"(b[0]), "r"(b[1]));
}
__device__ __forceinline__ uint32_t smem_u32(const void* p) {
    return (uint32_t)__cvta_generic_to_shared(p);
}
__device__ __forceinline__ void cpa16(uint32_t dst, const void* src) {
    asm volatile("cp.async.cg.shared.global [%0], [%1], 16;" :: "r"(dst), "l"(src));
}
__device__ __forceinline__ void cp_commit() { asm volatile("cp.async.commit_group;"); }
template <int N> __device__ __forceinline__ void cp_wait() {
    asm volatile("cp.async.wait_group %0;" :: "n"(N));
}

// ---------------- fp16 dense GEMM: BM=128 BN=64 BK=64, m16n8k16, 3-stage, 2 CTA/SM --------
// BK=64 halves the serialized wait/barrier events per CTA vs BK=32; accumulation
// order per accumulator is the same ascending k16 sequence -> bit-identical results.
#define LAH 72
#define LBH 72
#define STGH 3
#define STAGE_H (128 * LAH + 64 * LBH)      // halves = 13824 (27648 B)
#define SM_GH (STGH * STAGE_H * 2)          // 82944 B

template <int EPI>
__device__ __forceinline__ void gemm_core_h(
    const __half* __restrict__ A, const __half* __restrict__ Bt,
    void* __restrict__ Cv, const float* __restrict__ E, const float* __restrict__ bv,
    __half* __restrict__ H2,
    int K, int lda, int ldb, int ldc, int row0, int col0, __half* smh) {

    const int tid = threadIdx.x, wid = tid >> 5, lane = tid & 31;
    const int gid = lane >> 2, tg = lane & 3;
    const int wm0 = (wid >> 1) * 32, wn0 = (wid & 1) * 32;

    float acc[2][4][4];
#pragma unroll
    for (int i = 0; i < 2; i++)
#pragma unroll
        for (int j = 0; j < 4; j++)
#pragma unroll
            for (int k = 0; k < 4; k++) acc[i][j][k] = 0.0f;

    auto issue = [&](int buf, int t) {
        int k0 = t * 64;
        uint32_t as = smem_u32(smh + buf * STAGE_H);
        uint32_t bs = as + 128 * LAH * 2;
#pragma unroll
        for (int i = 0; i < 4; i++) {              // A: 128 rows x 64k / 8 / 256 = 4
            int q = tid + i * 256;
            int m = q >> 3, c16 = q & 7;
            cpa16(as + (m * LAH + c16 * 8) * 2,
                  A + (long)(row0 + m) * lda + k0 + c16 * 8);
        }
#pragma unroll
        for (int i = 0; i < 2; i++) {              // B: 64 rows x 64k / 8 / 256 = 2
            int q = tid + i * 256;
            int n = q >> 3, c16 = q & 7;
            cpa16(bs + (n * LBH + c16 * 8) * 2,
                  Bt + (long)(col0 + n) * ldb + k0 + c16 * 8);
        }
        cp_commit();
    };
    auto compute = [&](int buf) {
        const __half* ab = smh + buf * STAGE_H;
        const __half* bb = ab + 128 * LAH;
#pragma unroll
        for (int ks = 0; ks < 64; ks += 16) {
            uint32_t af[2][4], bf[4][2];
#pragma unroll
            for (int mt = 0; mt < 2; mt++) {
                const __half* p = ab + (wm0 + mt * 16 + gid) * LAH + ks + 2 * tg;
                af[mt][0] = *(const uint32_t*)p;
                af[mt][1] = *(const uint32_t*)(p + 8 * LAH);
                af[mt][2] = *(const uint32_t*)(p + 8);
                af[mt][3] = *(const uint32_t*)(p + 8 * LAH + 8);
            }
#pragma unroll
            for (int nt = 0; nt < 4; nt++) {
                const __half* p = bb + (wn0 + nt * 8 + gid) * LBH + ks + 2 * tg;
                bf[nt][0] = *(const uint32_t*)p;
                bf[nt][1] = *(const uint32_t*)(p + 8);
            }
#pragma unroll
            for (int mt = 0; mt < 2; mt++)
#pragma unroll
                for (int nt = 0; nt < 4; nt++)
                    mma_f16(acc[mt][nt], af[mt], bf[nt]);
        }
    };

    const int TILES = K / 64;                 // >= 4 for all our shapes
    issue(0, 0);
    issue(1, 1);
    int buf = 0, nxt = 2;
    for (int t = 0; t < TILES; t++) {
        cp_wait<STGH - 2>();
        __syncthreads();
        if (t + STGH - 1 < TILES) issue(nxt, t + STGH - 1);
        else cp_commit();
        compute(buf);
        buf = (buf + 1 == STGH) ? 0 : buf + 1;
        nxt = (nxt + 1 == STGH) ? 0 : nxt + 1;
        // single barrier per tile (validated R13)
    }

#pragma unroll
    for (int mt = 0; mt < 2; mt++)
#pragma unroll
        for (int nt = 0; nt < 4; nt++)
#pragma unroll
            for (int half = 0; half < 2; half++) {
                int r = row0 + wm0 + mt * 16 + gid + half * 8;
                int c = col0 + wn0 + nt * 8 + 2 * tg;
                float v0 = acc[mt][nt][half * 2 + 0];
                float v1 = acc[mt][nt][half * 2 + 1];
                if (EPI == 4) {
                    *(__half2*)((__half*)Cv + (long)r * ldc + c) = __floats2half2_rn(v0, v1);
                } else if (EPI == 5) {
                    __half* H = (__half*)Cv;
                    int bb2 = r >> 10, rl = r & 1023;
                    H[((long)bb2 * DIM + c) * NN_ + rl] = __float2half_rn(v0);
                    H[((long)bb2 * DIM + c + 1) * NN_ + rl] = __float2half_rn(v1);
                } else if (EPI == 3) {
                    v0 += bv[c];
                    v1 += bv[c + 1];
                    v0 = 0.5f * v0 * (1.0f + erff(v0 * 0.70710678118654752f));
                    v1 = 0.5f * v1 * (1.0f + erff(v1 * 0.70710678118654752f));
                    *(__half2*)((__half*)Cv + (long)r * ldc + c) = __floats2half2_rn(v0, v1);
                } else {
                    long off = (long)r * ldc + c;
                    if (EPI == 2 || EPI == 6) {
                        float2 e = *(const float2*)(E + off);
                        v0 += e.x + bv[c];
                        v1 += e.y + bv[c + 1];
                    }
                    float2 o; o.x = v0; o.y = v1;
                    *(float2*)((float*)Cv + off) = o;
                    if (EPI == 6) {
                        int bb2 = r >> 10, rl = r & 1023;
                        H2[((long)bb2 * DIM + c) * NN_ + rl] = __float2half_rn(v0);
                        H2[((long)bb2 * DIM + c + 1) * NN_ + rl] = __float2half_rn(v1);
                    }
                }
            }
}

template <int EPI>
__global__ __launch_bounds__(256, 2)
void mma_gemm_h(const __half* __restrict__ A, const __half* __restrict__ Bt,
                void* __restrict__ C, const float* __restrict__ E,
                const float* __restrict__ bv, __half* __restrict__ H2,
                int K, int lda, int ldb, int ldc,
                long Ab, long Bb, long Cb) {
    extern __shared__ __align__(16) __half smh[];
    int z = blockIdx.z;
    A += (long)z * Ab;
    Bt += (long)z * Bb;
    void* Cz = (EPI == 3 || EPI == 4 || EPI == 5)
               ? (void*)((__half*)C + (long)z * Cb)
               : (void*)((float*)C + (long)z * Cb);
    gemm_core_h<EPI>(A, Bt, Cz, E, bv, H2,
                     K, lda, ldb, ldc, blockIdx.y * 128, blockIdx.x * 64, smh);
}

// merged kv + q: bx [0,4) -> K fp16; [4,8) -> V fp16 transposed; [8,12) -> Q fp16
__global__ __launch_bounds__(256, 2)
void kvq_gemm(const __half* __restrict__ xn, const __half* __restrict__ Wkvt,
              const __half* __restrict__ xma, const __half* __restrict__ Wqt) {
    extern __shared__ __align__(16) __half smh[];
    int row0 = blockIdx.y * 128;
    int bx = blockIdx.x;
    if (bx < 4)
        gemm_core_h<4>(xn, Wkvt, (void*)g_kh, nullptr, nullptr, nullptr,
                       DIM, DIM, DIM, DIM, row0, bx * 64, smh);
    else if (bx < 8)
        gemm_core_h<5>(xn, Wkvt + 256 * DIM, (void*)g_vth, nullptr, nullptr, nullptr,
                       DIM, DIM, DIM, 0, row0, (bx - 4) * 64, smh);
    else
        gemm_core_h<4>(xma, Wqt, (void*)g_qh, nullptr, nullptr, nullptr,
                       DIM, DIM, DIM, DIM, row0, (bx - 8) * 64, smh);
}

// ---------------- fused flash attention, fp16 (m16n8k16), bias prefetched to smem ---------
#define FL_SMEM ((128 * 72 + 2 * 128 * 72 + 2 * 64 * 136 + 2 * 128 * 136) * 2)

__global__ __launch_bounds__(256)
void flash_kernel(const __half* __restrict__ Qg, const __half* __restrict__ Kg,
                  const __half* __restrict__ Vtg, const __half* __restrict__ biasg,
                  __half* __restrict__ Og) {
    extern __shared__ __align__(16) __half smh[];
    __half* Qs = smh;
    __half* Ks = Qs + 128 * 72;
    __half* Vts = Ks + 2 * 128 * 72;
    __half* Bs = Vts + 2 * 64 * 136;

    const int i0 = blockIdx.x * 128;
    const int h = blockIdx.y, b = blockIdx.z;
    const __half* Qp = Qg + (long)b * NN_ * DIM + h * DH;
    const __half* Kp = Kg + (long)b * NN_ * DIM + h * DH;
    const __half* Vtp = Vtg + ((long)b * DIM + h * DH) * NN_;
    const __half* Bp = biasg + ((long)(b * HEADS + h)) * NN_ * NN_ + (long)i0 * NN_;

    const int tid = threadIdx.x, wid = tid >> 5, lane = tid & 31;
    const int gid = lane >> 2, tg = lane & 3;
    const int wm0 = wid * 16;

    auto issue_kv = [&](int buf, int j0) {
        uint32_t ks = smem_u32(Ks + buf * 128 * 72);
        uint32_t vs = smem_u32(Vts + buf * 64 * 136);
        uint32_t bsm = smem_u32(Bs + buf * 128 * 136);
#pragma unroll
        for (int t = 0; t < 4; t++) {
            int q = tid + t * 256;
            int n = q >> 3, c8 = q & 7;
            cpa16(ks + (n * 72 + c8 * 8) * 2, Kp + (long)(j0 + n) * DIM + c8 * 8);
        }
#pragma unroll
        for (int t = 0; t < 4; t++) {
            int q = tid + t * 256;
            int r = q >> 4, c16 = q & 15;
            cpa16(vs + (r * 136 + c16 * 8) * 2, Vtp + (long)r * NN_ + j0 + c16 * 8);
        }
#pragma unroll
        for (int t = 0; t < 8; t++) {
            int q = tid + t * 256;
            int r = q >> 4, c16 = q & 15;
            cpa16(bsm + (r * 136 + c16 * 8) * 2, Bp + (long)r * NN_ + j0 + c16 * 8);
        }
        cp_commit();
    };

    issue_kv(0, 0);

#pragma unroll
    for (int t = 0; t < 4; t++) {
        int q = tid + t * 256;
        int m = q >> 3, c8 = q & 7;
        *(uint4*)(Qs + m * 72 + c8 * 8) = *(const uint4*)(Qp + (long)(i0 + m) * DIM + c8 * 8);
    }

    float oacc[8][4];
#pragma unroll
    for (int i = 0; i < 8; i++)
#pragma unroll
        for (int j = 0; j < 4; j++) oacc[i][j] = 0.0f;
    float li0 = 0.0f, li1 = 0.0f;

    for (int t = 0; t < NN_ / 128; t++) {
        const int j0 = t * 128;
        const int buf = t & 1;
        cp_wait<0>();
        __syncthreads();
        if (t + 1 < NN_ / 128) issue_kv(buf ^ 1, j0 + 128);

        const __half* kb = Ks + buf * 128 * 72;
        const __half* vb = Vts + buf * 64 * 136;
        const __half* bsm = Bs + buf * 128 * 136;

        float s[16][4];
#pragma unroll
        for (int i = 0; i < 16; i++)
#pragma unroll
            for (int j = 0; j < 4; j++) s[i][j] = 0.0f;
#pragma unroll
        for (int ks = 0; ks < 64; ks += 16) {
            uint32_t a[4];
            const __half* pa = Qs + (wm0 + gid) * 72 + ks + 2 * tg;
            a[0] = *(const uint32_t*)pa;
            a[1] = *(const uint32_t*)(pa + 8 * 72);
            a[2] = *(const uint32_t*)(pa + 8);
            a[3] = *(const uint32_t*)(pa + 8 * 72 + 8);
#pragma unroll
            for (int nt = 0; nt < 16; nt++) {
                const __half* pb = kb + (nt * 8 + gid) * 72 + ks + 2 * tg;
                uint32_t bf[2] = { *(const uint32_t*)pb, *(const uint32_t*)(pb + 8) };
                mma_f16(s[nt], a, bf);
            }
        }

#pragma unroll
        for (int nt = 0; nt < 16; nt++) {
            const __half* pb0 = bsm + (wm0 + gid) * 136 + nt * 8 + 2 * tg;
            float2 e0 = __half22float2(*(const __half2*)pb0);
            float2 e1 = __half22float2(*(const __half2*)(pb0 + 8 * 136));
            s[nt][0] = __expf(fmaf(s[nt][0], SCALE, e0.x)); li0 += s[nt][0];
            s[nt][1] = __expf(fmaf(s[nt][1], SCALE, e0.y)); li0 += s[nt][1];
            s[nt][2] = __expf(fmaf(s[nt][2], SCALE, e1.x)); li1 += s[nt][2];
            s[nt][3] = __expf(fmaf(s[nt][3], SCALE, e1.y)); li1 += s[nt][3];
        }

#pragma unroll
        for (int ge = 0; ge < 16; ge += 2) {
            uint32_t pa4[4];
            pa4[0] = packh(s[ge][0], s[ge][1]);
            pa4[1] = packh(s[ge][2], s[ge][3]);
            pa4[2] = packh(s[ge + 1][0], s[ge + 1][1]);
            pa4[3] = packh(s[ge + 1][2], s[ge + 1][3]);
            int k0 = ge * 8;
#pragma unroll
            for (int nt = 0; nt < 8; nt++) {
                const __half* pb = vb + (nt * 8 + gid) * 136 + k0 + 2 * tg;
                uint32_t bf[2] = { *(const uint32_t*)pb, *(const uint32_t*)(pb + 8) };
                mma_f16(oacc[nt], pa4, bf);
            }
        }
    }

    li0 += __shfl_xor_sync(0xffffffffu, li0, 1);
    li0 += __shfl_xor_sync(0xffffffffu, li0, 2);
    li1 += __shfl_xor_sync(0xffffffffu, li1, 1);
    li1 += __shfl_xor_sync(0xffffffffu, li1, 2);
    float iv0 = 1.0f / li0, iv1 = 1.0f / li1;
#pragma unroll
    for (int nt = 0; nt < 8; nt++) {
        long off = ((long)b * NN_ + i0 + wm0 + gid) * DIM + h * DH + nt * 8 + 2 * tg;
        *(__half2*)(Og + off) = __floats2half2_rn(oacc[nt][0] * iv0, oacc[nt][1] * iv0);
        *(__half2*)(Og + off + 8 * DIM) = __floats2half2_rn(oacc[nt][2] * iv1, oacc[nt][3] * iv1);
    }
}

// ---------------- merged tiled transpose fp32 -> fp16 (all weights + x_in, one launch) ----
struct TJobs {
    const float* src[7];
    __half* dst[7];
    int K[7], N[7];
    int off[8];
};

__global__ void wtrans_all(TJobs J) {
    __shared__ float tile[32][33];
    int bid = blockIdx.x;
    int j = 0;
    while (bid >= J.off[j + 1]) j++;
    int local = bid - J.off[j];
    int K = J.K[j], N = J.N[j];
    int tn = N >> 5;
    int per_z = tn * (K >> 5);
    int z = local / per_z, rem = local % per_z;
    int n0 = (rem % tn) * 32, k0 = (rem / tn) * 32;
    const float* src = J.src[j] + (long)z * K * N;
    __half* dst = J.dst[j] + (long)z * K * N;
    int tx = threadIdx.x, ty = threadIdx.y;
#pragma unroll
    for (int i = 0; i < 32; i += 8)
        tile[ty + i][tx] = src[(long)(k0 + ty + i) * N + n0 + tx];
    __syncthreads();
#pragma unroll
    for (int i = 0; i < 32; i += 8)
        dst[(long)(n0 + ty + i) * K + k0 + tx] = __float2half_rn(tile[tx][ty + i]);
}

// ---------------- prep: add_attn(fp16) ; G = fp16(softmax(mean(b0)*mean(b1))) ----------
__global__ __launch_bounds__(256)
void prep_kernel(const float* __restrict__ ab) {
    __shared__ float sh[32];
    int b = blockIdx.x >> 10;
    int i = blockIdx.x & 1023;
    const long BHNN = (long)BB * HEADS * NN_ * NN_;
    int tid = threadIdx.x;
    int j4 = tid * 4;
    float4 sa = make_float4(0, 0, 0, 0), sb = make_float4(0, 0, 0, 0);
#pragma unroll
    for (int h = 0; h < HEADS; h++) {
        long o = (((long)(b * HEADS + h) * NN_) + i) * NN_ + j4;
        float4 a0 = *(const float4*)(ab + o);
        float4 a1 = *(const float4*)(ab + BHNN + o);
        sa.x += a0.x; sa.y += a0.y; sa.z += a0.z; sa.w += a0.w;
        sb.x += a1.x; sb.y += a1.y; sb.z += a1.z; sb.w += a1.w;
        union { __half2 h2[2]; uint2 u; } pk;
        pk.h2[0] = __floats2half2_rn(a0.x + a1.x, a0.y + a1.y);
        pk.h2[1] = __floats2half2_rn(a0.z + a1.z, a0.w + a1.w);
        *(uint2*)(&g_bias[o]) = pk.u;
    }
    float val[4];
    val[0] = (sa.x * 0.25f) * (sb.x * 0.25f);
    val[1] = (sa.y * 0.25f) * (sb.y * 0.25f);
    val[2] = (sa.z * 0.25f) * (sb.z * 0.25f);
    val[3] = (sa.w * 0.25f) * (sb.w * 0.25f);
    float m = fmaxf(fmaxf(val[0], val[1]), fmaxf(val[2], val[3]));
    m = block_max(m, sh);
    float s = 0.0f;
#pragma unroll
    for (int t = 0; t < 4; t++) { val[t] = __expf(val[t] - m); s += val[t]; }
    s = block_sum(s, sh);
    float inv = 1.0f / s;
    long rowo = ((long)(b * NN_ + i)) * NN_ + j4;
    union { __half2 h2[2]; uint2 u; } gk;
    gk.h2[0] = __floats2half2_rn(val[0] * inv, val[1] * inv);
    gk.h2[1] = __floats2half2_rn(val[2] * inv, val[3] * inv);
    *(uint2*)(&g_Gh[rowo]) = gk.u;
}

// ---------------- LayerNorm: one warp/row, one-pass; fp16 output ----------------
__device__ __forceinline__ void ln_row(const float* __restrict__ in, __half* __restrict__ out,
                                       const float* __restrict__ g, const float* __restrict__ bt,
                                       long row, int lane, int relu) {
    const float* p = in + row * DIM + lane * 8;
    float4 v0 = *(const float4*)p;
    float4 v1 = *(const float4*)(p + 4);
    float s = v0.x + v0.y + v0.z + v0.w + v1.x + v1.y + v1.z + v1.w;
    float q = v0.x * v0.x + v0.y * v0.y + v0.z * v0.z + v0.w * v0.w
            + v1.x * v1.x + v1.y * v1.y + v1.z * v1.z + v1.w * v1.w;
#pragma unroll
    for (int o = 16; o; o >>= 1) {
        s += __shfl_xor_sync(0xffffffffu, s, o);
        q += __shfl_xor_sync(0xffffffffu, q, o);
    }
    float mean = s * (1.0f / DIM);
    float var = q * (1.0f / DIM) - mean * mean;
    float rstd = rsqrtf(var + EPS);
    const float* gp = g + lane * 8;
    const float* bp = bt + lane * 8;
    float4 g0 = *(const float4*)gp, g1 = *(const float4*)(gp + 4);
    float4 b0 = *(const float4*)bp, b1 = *(const float4*)(bp + 4);
    float o8[8];
    o8[0] = (v0.x - mean) * rstd * g0.x + b0.x; o8[1] = (v0.y - mean) * rstd * g0.y + b0.y;
    o8[2] = (v0.z - mean) * rstd * g0.z + b0.z; o8[3] = (v0.w - mean) * rstd * g0.w + b0.w;
    o8[4] = (v1.x - mean) * rstd * g1.x + b1.x; o8[5] = (v1.y - mean) * rstd * g1.y + b1.y;
    o8[6] = (v1.z - mean) * rstd * g1.z + b1.z; o8[7] = (v1.w - mean) * rstd * g1.w + b1.w;
    if (relu) {
#pragma unroll
        for (int t = 0; t < 8; t++) o8[t] = fmaxf(o8[t], 0.0f);
    }
    union { __half2 h2[4]; uint4 u; } pk;
    pk.h2[0] = __floats2half2_rn(o8[0], o8[1]);
    pk.h2[1] = __floats2half2_rn(o8[2], o8[3]);
    pk.h2[2] = __floats2half2_rn(o8[4], o8[5]);
    pk.h2[3] = __floats2half2_rn(o8[6], o8[7]);
    *(uint4*)(out + row * DIM + lane * 8) = pk.u;
}

__global__ __launch_bounds__(256)
void ln_one(const float* __restrict__ in, __half* __restrict__ out,
            const float* __restrict__ g, const float* __restrict__ bt) {
    int w = threadIdx.x >> 5, lane = threadIdx.x & 31;
    ln_row(in, out, g, bt, (long)blockIdx.x * 8 + w, lane, 0);
}

__global__ __launch_bounds__(256)
void ln_fused(const float* __restrict__ inA, __half* __restrict__ outA,
              const float* __restrict__ gA, const float* __restrict__ bA,
              const float* __restrict__ inB, __half* __restrict__ outB,
              const float* __restrict__ gB, const float* __restrict__ bB, int nA) {
    int w = threadIdx.x >> 5, lane = threadIdx.x & 31;
    int bid = blockIdx.x;
    if (bid < nA)
        ln_row(inA, outA, gA, bA, (long)bid * 8 + w, lane, 1);
    else
        ln_row(inB, outB, gB, bB, (long)(bid - nA) * 8 + w, lane, 0);
}

// ---------------- host ----------------
extern "C" void kernel_launch(void* const* d_in, const int* in_sizes, int n_in,
                              void* d_out, int out_size) {
    const float* x_in   = (const float*)d_in[0];
    const float* abias  = (const float*)d_in[1];
    const float* ln1_g  = (const float*)d_in[2];
    const float* ln1_b  = (const float*)d_in[3];
    const float* Wkv    = (const float*)d_in[4];
    const float* Wq     = (const float*)d_in[5];
    const float* Wo     = (const float*)d_in[6];
    const float* bo     = (const float*)d_in[7];
    const float* ln2_g  = (const float*)d_in[8];
    const float* ln2_b  = (const float*)d_in[9];
    const float* W1     = (const float*)d_in[10];
    const float* b1     = (const float*)d_in[11];
    const float* W2     = (const float*)d_in[12];
    const float* b2     = (const float*)d_in[13];
    const float* Wg     = (const float*)d_in[14];
    const float* lng_g  = (const float*)d_in[15];
    const float* lng_b  = (const float*)d_in[16];
    float* out = (float*)d_out;

    float *px, *pxma;
    __half *pGh, *pbias, *pxnh, *pxmah, *pgxh, *paoh, *pffh, *pxth, *pkh, *pqh, *pvth, *pwh;
    cudaGetSymbolAddress((void**)&px, g_x);
    cudaGetSymbolAddress((void**)&pxma, g_xma);
    cudaGetSymbolAddress((void**)&pGh, g_Gh);
    cudaGetSymbolAddress((void**)&pbias, g_bias);
    cudaGetSymbolAddress((void**)&pxnh, g_xnh);
    cudaGetSymbolAddress((void**)&pxmah, g_xmah);
    cudaGetSymbolAddress((void**)&pgxh, g_gxh);
    cudaGetSymbolAddress((void**)&paoh, g_aoh);
    cudaGetSymbolAddress((void**)&pffh, g_ffh);
    cudaGetSymbolAddress((void**)&pxth, g_xth);
    cudaGetSymbolAddress((void**)&pkh, g_kh);
    cudaGetSymbolAddress((void**)&pqh, g_qh);
    cudaGetSymbolAddress((void**)&pvth, g_vth);
    cudaGetSymbolAddress((void**)&pwh, g_wh);

    const int ROWS = BB * NN_;           // 4096
    const long ND = (long)NN_ * DIM;
    dim3 blk(256);
    dim3 tblk(32, 8);

    cudaFuncSetAttribute(mma_gemm_h<0>, cudaFuncAttributeMaxDynamicSharedMemorySize, SM_GH);
    cudaFuncSetAttribute(mma_gemm_h<2>, cudaFuncAttributeMaxDynamicSharedMemorySize, SM_GH);
    cudaFuncSetAttribute(mma_gemm_h<3>, cudaFuncAttributeMaxDynamicSharedMemorySize, SM_GH);
    cudaFuncSetAttribute(mma_gemm_h<4>, cudaFuncAttributeMaxDynamicSharedMemorySize, SM_GH);
    cudaFuncSetAttribute(mma_gemm_h<6>, cudaFuncAttributeMaxDynamicSharedMemorySize, SM_GH);
    cudaFuncSetAttribute(kvq_gemm, cudaFuncAttributeMaxDynamicSharedMemorySize, SM_GH);
    cudaFuncSetAttribute(flash_kernel, cudaFuncAttributeMaxDynamicSharedMemorySize, FL_SMEM);

    // one merged transpose launch: 6 weight tensors + x_in -> x^T
    TJobs J;
    J.src[0] = Wkv;  J.dst[0] = pwh + OW_KV; J.K[0] = 256;  J.N[0] = 512;
    J.src[1] = Wq;   J.dst[1] = pwh + OW_Q;  J.K[1] = 256;  J.N[1] = 256;
    J.src[2] = Wo;   J.dst[2] = pwh + OW_O;  J.K[2] = 256;  J.N[2] = 256;
    J.src[3] = W1;   J.dst[3] = pwh + OW_1;  J.K[3] = 256;  J.N[3] = 1024;
    J.src[4] = W2;   J.dst[4] = pwh + OW_2;  J.K[4] = 1024; J.N[4] = 256;
    J.src[5] = Wg;   J.dst[5] = pwh + OW_G;  J.K[5] = 256;  J.N[5] = 256;
    J.src[6] = x_in; J.dst[6] = pxth;        J.K[6] = 1024; J.N[6] = 256;
    int nz[7] = {DEPTH, DEPTH, DEPTH, DEPTH, DEPTH, 1, BB};
    J.off[0] = 0;
    for (int j = 0; j < 7; j++)
        J.off[j + 1] = J.off[j] + nz[j] * (J.N[j] >> 5) * (J.K[j] >> 5);
    wtrans_all<<<J.off[7], tblk>>>(J);

    prep_kernel<<<BB * NN_, blk>>>(abias);

    for (int l = 0; l < DEPTH; l++) {
        const float* xcur = (l == 0) ? x_in : px;
        // GX = G @ x -> gxh fp16
        mma_gemm_h<4><<<dim3(DIM / 64, NN_ / 128, BB), blk, SM_GH>>>(
            pGh, pxth, pgxh, nullptr, nullptr, nullptr,
            NN_, NN_, NN_, DIM, (long)NN_ * NN_, (long)DIM * NN_, ND);
        // x_ma_pre = GX @ Wg -> g_xma fp32
        mma_gemm_h<0><<<dim3(DIM / 64, ROWS / 128, 1), blk, SM_GH>>>(
            pgxh, pwh + OW_G, pxma, nullptr, nullptr, nullptr,
            DIM, DIM, DIM, DIM, 0, 0, 0);
        // merged: xmah = relu(LN(xma)) ; xnh = LN(x)
        ln_fused<<<ROWS / 4, blk>>>(pxma, pxmah, lng_g, lng_b,
                                    xcur, pxnh, ln1_g + l * DIM, ln1_b + l * DIM, ROWS / 8);
        // merged K/V/Q -> fp16 (V transposed)
        kvq_gemm<<<dim3(12, ROWS / 128, 1), blk, SM_GH>>>(
            pxnh, pwh + OW_KV + (long)l * 512 * DIM,
            pxmah, pwh + OW_Q + (long)l * DIM * DIM);
        // fused fp16 attention -> aoh
        flash_kernel<<<dim3(NN_ / 128, HEADS, BB), blk, FL_SMEM>>>(pqh, pkh, pvth, pbias, paoh);
        // x = x + ao @ Wo[l] + bo[l]
        mma_gemm_h<2><<<dim3(DIM / 64, ROWS / 128, 1), blk, SM_GH>>>(
            paoh, pwh + OW_O + (long)l * DIM * DIM, px, xcur, bo + l * DIM, nullptr,
            DIM, DIM, DIM, DIM, 0, 0, 0);
        // xn2 = LN(x) -> xnh
        ln_one<<<ROWS / 8, blk>>>(px, pxnh, ln2_g + l * DIM, ln2_b + l * DIM);
        // ff = gelu(xn2 @ W1[l] + b1[l]) -> ffh fp16
        mma_gemm_h<3><<<dim3(MLP / 64, ROWS / 128, 1), blk, SM_GH>>>(
            pxnh, pwh + OW_1 + (long)l * MLP * DIM, pffh, nullptr, b1 + l * MLP, nullptr,
            DIM, DIM, DIM, MLP, 0, 0, 0);
        // x = x + ff @ W2[l] + b2[l]; also x^T fp16 for next GX
        if (l == DEPTH - 1) {
            mma_gemm_h<2><<<dim3(DIM / 64, ROWS / 128, 1), blk, SM_GH>>>(
                pffh, pwh + OW_2 + (long)l * DIM * MLP, out, px, b2 + l * DIM, nullptr,
                MLP, MLP, MLP, DIM, 0, 0, 0);
        } else {
            mma_gemm_h<6><<<dim3(DIM / 64, ROWS / 128, 1), blk, SM_GH>>>(
                pffh, pwh + OW_2 + (long)l * DIM * MLP, px, px, b2 + l * DIM, pxth,
                MLP, MLP, MLP, DIM, 0, 0, 0);
        }
    }
}